// round 11
// baseline (speedup 1.0000x reference)
#include <cuda_runtime.h>
#include <cuda_fp16.h>
#include <stdint.h>
#include <math.h>

// ---------------------------------------------------------------------------
// Problem constants
// ---------------------------------------------------------------------------
constexpr int BATCH = 8;
constexpr int SEQ   = 2048;
constexpr int EMB   = 1024;
constexpr size_t MT = (size_t)BATCH * SEQ;            // 16384

// ---------------------------------------------------------------------------
// Scratch (static device arrays -- allocation-free per harness rules)
// ---------------------------------------------------------------------------
__device__ __half g_T16[MT * EMB];                    // target fp16
__device__ __half g_U16[MT * EMB];                    // source fp16
__device__ __half g_W16[4][(size_t)EMB * EMB];        // Wq,Wk,Wv,Wo fp16
__device__ __half g_Q16[MT * EMB];
__device__ __half g_K16[MT * EMB];
__device__ __half g_V16[MT * EMB];
__device__ __half g_Vt [MT * EMB];                    // V^T  [b][e][s]
__device__ __half g_O16[MT * EMB];
__device__ __half g_S16[(size_t)BATCH * SEQ * SEQ];   // scores fp16
__device__ __half g_P16[(size_t)BATCH * SEQ * SEQ];   // probs fp16

// ---------------------------------------------------------------------------
// Helpers
// ---------------------------------------------------------------------------
__device__ __forceinline__ uint32_t smem_u32(const void* p) {
    uint32_t a;
    asm("{ .reg .u64 t; cvta.to.shared.u64 t, %1; cvt.u32.u64 %0, t; }" : "=r"(a) : "l"(p));
    return a;
}

__device__ __forceinline__ void cp16(uint32_t sdst, const void* gsrc) {
    asm volatile("cp.async.cg.shared.global [%0], [%1], 16;" :: "r"(sdst), "l"(gsrc));
}

__device__ __forceinline__ void ldsm4(uint32_t addr, uint32_t& r0, uint32_t& r1,
                                      uint32_t& r2, uint32_t& r3) {
    asm volatile("ldmatrix.sync.aligned.m8n8.x4.shared.b16 {%0,%1,%2,%3}, [%4];"
                 : "=r"(r0), "=r"(r1), "=r"(r2), "=r"(r3) : "r"(addr));
}

// ---------------------------------------------------------------------------
// Fused fp32 -> fp16 conversion over all six tensors (one launch).
// ---------------------------------------------------------------------------
struct CvtArgs {
    const float* in[6];
    __half*      out[6];
};

__global__ __launch_bounds__(256) void cvt_all(CvtArgs a) {
    constexpr size_t NB = 2097152;        // groups per big tensor (MT*EMB/8)
    constexpr size_t NW = 131072;         // groups per weight (EMB*EMB/8)
    size_t i = (size_t)blockIdx.x * blockDim.x + threadIdx.x;
    const float* x; __half* y; size_t off;
    if (i < NB)            { x = a.in[0]; y = a.out[0]; off = i; }
    else if (i < 2 * NB)   { x = a.in[1]; y = a.out[1]; off = i - NB; }
    else {
        size_t j = i - 2 * NB;
        if (j >= 4 * NW) return;
        int w = (int)(j / NW);
        x = a.in[2 + w]; y = a.out[2 + w]; off = j - (size_t)w * NW;
    }
    float4 p = ((const float4*)x)[2 * off];
    float4 q = ((const float4*)x)[2 * off + 1];
    __half2 h[4];
    h[0] = __floats2half2_rn(p.x, p.y);
    h[1] = __floats2half2_rn(p.z, p.w);
    h[2] = __floats2half2_rn(q.x, q.y);
    h[3] = __floats2half2_rn(q.z, q.w);
    ((uint4*)y)[off] = *(uint4*)h;
}

// ---------------------------------------------------------------------------
// fp16 transpose: in [SEQ][EMB] per batch  ->  out [EMB][SEQ] per batch
// ---------------------------------------------------------------------------
__global__ __launch_bounds__(1024) void transpose_h(const __half* __restrict__ in,
                                                    __half* __restrict__ out) {
    __shared__ __half t[32][33];
    const size_t zoff = (size_t)blockIdx.z * SEQ * EMB;
    const int tx = threadIdx.x, ty = threadIdx.y;
    int s = blockIdx.y * 32 + ty;
    int e = blockIdx.x * 32 + tx;
    t[ty][tx] = in[zoff + (size_t)s * EMB + e];
    __syncthreads();
    int eo = blockIdx.x * 32 + ty;
    int so = blockIdx.y * 32 + tx;
    out[zoff + (size_t)eo * SEQ + so] = t[tx][ty];
}

// ---------------------------------------------------------------------------
// HMMA GEMM:  C[m,n] = scale * sum_k A[m,k] * B[n,k]  (+ bias[n])
//   A: fp16, row-major [M][K] (ldA)     B: fp16, row-major [N][K] (ldB)
//   EPI==0: fp32 out      EPI==1: fp16 out     (batched by z)
// CTA tile 128x128, BK=64, 8 warps (2x4 grid of 64x32 warp tiles),
// cp.async double-buffered smem (dynamic), ldmatrix, m16n8k16 HMMA.
// Round-6 known-good mainloop; 2 CTAs/SM co-tenancy is load-bearing.
// ---------------------------------------------------------------------------
constexpr int RS = 72;                         // smem row stride (64 + 8 pad)
constexpr int TILE  = 128 * RS * 2;            // 18432 B per tile
constexpr int STAGE = 2 * TILE;                // A + B per stage
constexpr int GEMM_SMEM = 2 * STAGE;           // 73728 B

template <int EPI>
__global__ void __launch_bounds__(256, 2) mma_gemm(
    const __half* __restrict__ A, const __half* __restrict__ B,
    const float* __restrict__ bias, float scale,
    float* __restrict__ Cf, __half* __restrict__ Ch,
    int K, int ldA, int ldB, int ldC,
    size_t strA, size_t strB, size_t strC)
{
    extern __shared__ __align__(16) char smem[];

    const int tid  = threadIdx.x;
    const int lane = tid & 31;
    const int wid  = tid >> 5;
    const int wm   = (wid >> 2) * 64;      // warp m offset in tile
    const int wn   = (wid & 3) * 32;       // warp n offset in tile
    const int bm   = blockIdx.y * 128;
    const int bn   = blockIdx.x * 128;
    const int bz   = blockIdx.z;

    A += (size_t)bz * strA;
    B += (size_t)bz * strB;

    const uint32_t sbase = smem_u32(smem);
    const uint32_t sA[2] = { sbase,         sbase + STAGE };
    const uint32_t sB[2] = { sbase + TILE,  sbase + STAGE + TILE };

    // copy one 128x64 fp16 tile (16KB data) : 4 cp.async per thread
    auto load_tile = [&](uint32_t sdst, const __half* src, int ld, int rowBase, int k0) {
#pragma unroll
        for (int i = 0; i < 4; i++) {
            int c  = tid + i * 256;        // 0..1023
            int r  = c >> 3;               // 0..127
            int kc = (c & 7) * 8;          // 0..56
            cp16(sdst + (uint32_t)(r * RS + kc) * 2,
                 src + (size_t)(rowBase + r) * ld + k0 + kc);
        }
    };

    float acc[4][4][4];
#pragma unroll
    for (int i = 0; i < 4; i++)
#pragma unroll
        for (int j = 0; j < 4; j++)
#pragma unroll
            for (int q = 0; q < 4; q++) acc[i][j][q] = 0.f;

    const int nk = K >> 6;

    // prefetch chunk 0
    load_tile(sA[0], A, ldA, bm, 0);
    load_tile(sB[0], B, ldB, bn, 0);
    asm volatile("cp.async.commit_group;");

    for (int c = 0; c < nk; c++) {
        const int buf = c & 1;
        asm volatile("cp.async.wait_group 0;");
        __syncthreads();

        if (c + 1 < nk) {
            const int k0 = (c + 1) << 6;
            load_tile(sA[buf ^ 1], A, ldA, bm, k0);
            load_tile(sB[buf ^ 1], B, ldB, bn, k0);
            asm volatile("cp.async.commit_group;");
        }

        // compute on buf: four k16 steps
#pragma unroll
        for (int ks = 0; ks < 64; ks += 16) {
            uint32_t a[4][4];
#pragma unroll
            for (int i = 0; i < 4; i++) {
                uint32_t addr = sA[buf] +
                    (uint32_t)((wm + i * 16 + (lane & 15)) * RS + ks + ((lane >> 4) << 3)) * 2;
                ldsm4(addr, a[i][0], a[i][1], a[i][2], a[i][3]);
            }
            uint32_t b[4][2];
#pragma unroll
            for (int jj = 0; jj < 2; jj++) {
                int row = wn + jj * 16 + (lane & 7) + ((lane >> 4) << 3);
                int col = ks + (((lane >> 3) & 1) << 3);
                uint32_t addr = sB[buf] + (uint32_t)(row * RS + col) * 2;
                uint32_t r0, r1, r2, r3;
                ldsm4(addr, r0, r1, r2, r3);
                b[2 * jj][0] = r0; b[2 * jj][1] = r1;
                b[2 * jj + 1][0] = r2; b[2 * jj + 1][1] = r3;
            }
#pragma unroll
            for (int i = 0; i < 4; i++)
#pragma unroll
                for (int j = 0; j < 4; j++) {
                    asm volatile(
                        "mma.sync.aligned.m16n8k16.row.col.f32.f16.f16.f32 "
                        "{%0,%1,%2,%3},{%4,%5,%6,%7},{%8,%9},{%0,%1,%2,%3};"
                        : "+f"(acc[i][j][0]), "+f"(acc[i][j][1]),
                          "+f"(acc[i][j][2]), "+f"(acc[i][j][3])
                        : "r"(a[i][0]), "r"(a[i][1]), "r"(a[i][2]), "r"(a[i][3]),
                          "r"(b[j][0]), "r"(b[j][1]));
                }
        }
        __syncthreads();
    }

    // Epilogue
#pragma unroll
    for (int i = 0; i < 4; i++) {
        const int r0 = bm + wm + i * 16 + (lane >> 2);
#pragma unroll
        for (int j = 0; j < 4; j++) {
            const int c0 = bn + wn + j * 8 + 2 * (lane & 3);
            float bia0 = bias ? bias[c0]     : 0.f;
            float bia1 = bias ? bias[c0 + 1] : 0.f;
            float v0 = acc[i][j][0] * scale + bia0;
            float v1 = acc[i][j][1] * scale + bia1;
            float v2 = acc[i][j][2] * scale + bia0;
            float v3 = acc[i][j][3] * scale + bia1;
            const size_t base0 = (size_t)bz * strC + (size_t)r0 * ldC + c0;
            const size_t base1 = base0 + (size_t)8 * ldC;
            if (EPI == 0) {
                *(float2*)(Cf + base0) = make_float2(v0, v1);
                *(float2*)(Cf + base1) = make_float2(v2, v3);
            } else {
                *(__half2*)(Ch + base0) = __floats2half2_rn(v0, v1);
                *(__half2*)(Ch + base1) = __floats2half2_rn(v2, v3);
            }
        }
    }
}

// ---------------------------------------------------------------------------
// Row softmax over length-2048 fp16 rows -> fp16 probabilities
// ---------------------------------------------------------------------------
__global__ __launch_bounds__(256) void softmax_rows(const __half* __restrict__ S,
                                                    __half* __restrict__ P)
{
    const size_t row = blockIdx.x;
    const int tid = threadIdx.x;

    uint4 raw = ((const uint4*)(S + row * (size_t)SEQ))[tid];
    const __half2* hp = (const __half2*)&raw;
    float v[8];
#pragma unroll
    for (int g = 0; g < 4; g++) {
        float2 f = __half22float2(hp[g]);
        v[2 * g] = f.x; v[2 * g + 1] = f.y;
    }

    float m = v[0];
#pragma unroll
    for (int i = 1; i < 8; i++) m = fmaxf(m, v[i]);
#pragma unroll
    for (int o = 16; o > 0; o >>= 1) m = fmaxf(m, __shfl_xor_sync(0xFFFFFFFFu, m, o));
    __shared__ float red[8];
    if ((tid & 31) == 0) red[tid >> 5] = m;
    __syncthreads();
    m = red[0];
#pragma unroll
    for (int w = 1; w < 8; w++) m = fmaxf(m, red[w]);
    __syncthreads();

    float s = 0.f;
#pragma unroll
    for (int i = 0; i < 8; i++) { v[i] = __expf(v[i] - m); s += v[i]; }
#pragma unroll
    for (int o = 16; o > 0; o >>= 1) s += __shfl_xor_sync(0xFFFFFFFFu, s, o);
    if ((tid & 31) == 0) red[tid >> 5] = s;
    __syncthreads();
    s = 0.f;
#pragma unroll
    for (int w = 0; w < 8; w++) s += red[w];
    const float inv = 1.f / s;

    __half2 h[4];
#pragma unroll
    for (int g = 0; g < 4; g++)
        h[g] = __floats2half2_rn(v[2 * g] * inv, v[2 * g + 1] * inv);
    ((uint4*)(P + row * (size_t)SEQ))[tid] = *(uint4*)h;
}

// ---------------------------------------------------------------------------
// Launcher
// ---------------------------------------------------------------------------
extern "C" void kernel_launch(void* const* d_in, const int* in_sizes, int n_in,
                              void* d_out, int out_size)
{
    const float* target = (const float*)d_in[0];
    const float* source = (const float*)d_in[1];
    const float* Wq = (const float*)d_in[2];
    const float* bq = (const float*)d_in[3];
    const float* Wk = (const float*)d_in[4];
    const float* bk = (const float*)d_in[5];
    const float* Wv = (const float*)d_in[6];
    const float* bv = (const float*)d_in[7];
    const float* Wo = (const float*)d_in[8];
    const float* bo = (const float*)d_in[9];
    float* out = (float*)d_out;

    __half *pT, *pU, *pW, *pQ, *pK, *pV, *pVt, *pO, *pP, *pS;
    cudaGetSymbolAddress((void**)&pT,  g_T16);
    cudaGetSymbolAddress((void**)&pU,  g_U16);
    cudaGetSymbolAddress((void**)&pW,  g_W16);
    cudaGetSymbolAddress((void**)&pQ,  g_Q16);
    cudaGetSymbolAddress((void**)&pK,  g_K16);
    cudaGetSymbolAddress((void**)&pV,  g_V16);
    cudaGetSymbolAddress((void**)&pVt, g_Vt);
    cudaGetSymbolAddress((void**)&pO,  g_O16);
    cudaGetSymbolAddress((void**)&pP,  g_P16);
    cudaGetSymbolAddress((void**)&pS,  g_S16);

    cudaFuncSetAttribute(mma_gemm<0>, cudaFuncAttributeMaxDynamicSharedMemorySize, GEMM_SMEM);
    cudaFuncSetAttribute(mma_gemm<1>, cudaFuncAttributeMaxDynamicSharedMemorySize, GEMM_SMEM);

    const size_t WS = (size_t)EMB * EMB;
    const dim3 blk(256);

    // ---- fused fp32 -> fp16 conversions (one launch)
    {
        CvtArgs ca;
        ca.in[0] = target; ca.out[0] = pT;
        ca.in[1] = source; ca.out[1] = pU;
        ca.in[2] = Wq; ca.out[2] = pW + 0 * WS;
        ca.in[3] = Wk; ca.out[3] = pW + 1 * WS;
        ca.in[4] = Wv; ca.out[4] = pW + 2 * WS;
        ca.in[5] = Wo; ca.out[5] = pW + 3 * WS;
        size_t total = 2 * (MT * EMB / 8) + 4 * (WS / 8);
        cvt_all<<<(unsigned)((total + 255) / 256), blk>>>(ca);
    }

    const dim3 gProj(EMB / 128, (unsigned)(MT / 128), 1);   // 8 x 128

    // ---- projections: X @ W^T + b  -> fp16
    mma_gemm<1><<<gProj, blk, GEMM_SMEM>>>(pT, pW + 0 * WS, bq, 1.f, nullptr, pQ,
                                           EMB, EMB, EMB, EMB, 0, 0, 0);
    mma_gemm<1><<<gProj, blk, GEMM_SMEM>>>(pU, pW + 1 * WS, bk, 1.f, nullptr, pK,
                                           EMB, EMB, EMB, EMB, 0, 0, 0);
    mma_gemm<1><<<gProj, blk, GEMM_SMEM>>>(pU, pW + 2 * WS, bv, 1.f, nullptr, pV,
                                           EMB, EMB, EMB, EMB, 0, 0, 0);

    // ---- transpose V: [b][s][e] -> [b][e][s]
    transpose_h<<<dim3(EMB / 32, SEQ / 32, BATCH), dim3(32, 32)>>>(pV, pVt);

    // ---- scores: S[b] = Q[b] @ K[b]^T / 32   -> fp16
    mma_gemm<1><<<dim3(SEQ / 128, SEQ / 128, BATCH), blk, GEMM_SMEM>>>(
        pQ, pK, nullptr, 1.f / 32.f, nullptr, pS,
        EMB, EMB, EMB, SEQ,
        (size_t)SEQ * EMB, (size_t)SEQ * EMB, (size_t)SEQ * SEQ);

    // ---- softmax -> fp16 P
    softmax_rows<<<BATCH * SEQ, blk>>>(pS, pP);

    // ---- O[b] = P[b] @ Vt[b]^T   (Vt is [e][s], k-major in s)  -> fp16
    mma_gemm<1><<<dim3(EMB / 128, SEQ / 128, BATCH), blk, GEMM_SMEM>>>(
        pP, pVt, nullptr, 1.f, nullptr, pO,
        SEQ, SEQ, SEQ, EMB,
        (size_t)SEQ * SEQ, (size_t)SEQ * EMB, (size_t)SEQ * EMB);

    // ---- out = O @ Wo^T + bo  -> fp32
    mma_gemm<0><<<gProj, blk, GEMM_SMEM>>>(pO, pW + 3 * WS, bo, 1.f, out, nullptr,
                                           EMB, EMB, EMB, EMB, 0, 0, 0);
}

// round 16
// speedup vs baseline: 1.1217x; 1.1217x over previous
#include <cuda_runtime.h>
#include <cuda_fp16.h>
#include <stdint.h>
#include <math.h>

// ---------------------------------------------------------------------------
// Problem constants
// ---------------------------------------------------------------------------
constexpr int BATCH = 8;
constexpr int SEQ   = 2048;
constexpr int EMB   = 1024;
constexpr size_t MT = (size_t)BATCH * SEQ;            // 16384

// ---------------------------------------------------------------------------
// Scratch (static device arrays -- allocation-free per harness rules)
// ---------------------------------------------------------------------------
__device__ __half g_T16[MT * EMB];                    // target fp16
__device__ __half g_U16[MT * EMB];                    // source fp16
__device__ __half g_W16[4][(size_t)EMB * EMB];        // WqT, WkT, WvT, Wo (fp16)
__device__ __half g_G  [(size_t)EMB * EMB];           // G' = (Wq^T Wk)^T row-major [e][d]
__device__ __half g_H  [(size_t)EMB * EMB];           // H  = Wo Wv        row-major [o][e]
__device__ __half g_Q2 [MT * EMB];                    // T * G
__device__ __half g_V2 [MT * EMB];                    // U * H^T
__device__ __half g_Vt [MT * EMB];                    // V2^T  [b][o][s]
__device__ __half g_S16[(size_t)BATCH * SEQ * SEQ];   // scores fp16
__device__ __half g_P16[(size_t)BATCH * SEQ * SEQ];   // probs fp16
__device__ float  g_c  [(size_t)BATCH * SEQ];         // per-row score bias (col bias in S gemm)
__device__ float  g_w  [EMB];                         // Wk^T bq
__device__ float  g_b2 [EMB];                         // bo + Wo bv

// ---------------------------------------------------------------------------
// Helpers
// ---------------------------------------------------------------------------
__device__ __forceinline__ uint32_t smem_u32(const void* p) {
    uint32_t a;
    asm("{ .reg .u64 t; cvta.to.shared.u64 t, %1; cvt.u32.u64 %0, t; }" : "=r"(a) : "l"(p));
    return a;
}

__device__ __forceinline__ void cp16(uint32_t sdst, const void* gsrc) {
    asm volatile("cp.async.cg.shared.global [%0], [%1], 16;" :: "r"(sdst), "l"(gsrc));
}

__device__ __forceinline__ void ldsm4(uint32_t addr, uint32_t& r0, uint32_t& r1,
                                      uint32_t& r2, uint32_t& r3) {
    asm volatile("ldmatrix.sync.aligned.m8n8.x4.shared.b16 {%0,%1,%2,%3}, [%4];"
                 : "=r"(r0), "=r"(r1), "=r"(r2), "=r"(r3) : "r"(addr));
}

// ---------------------------------------------------------------------------
// fp32 -> fp16 conversion, 8 elems / thread (round-6 proven)
// ---------------------------------------------------------------------------
__global__ __launch_bounds__(256) void cvt_h(const float* __restrict__ x,
                                             __half* __restrict__ y, size_t n8) {
    size_t i = (size_t)blockIdx.x * blockDim.x + threadIdx.x;
    if (i >= n8) return;
    float4 a = ((const float4*)x)[2 * i];
    float4 b = ((const float4*)x)[2 * i + 1];
    __half2 h[4];
    h[0] = __floats2half2_rn(a.x, a.y);
    h[1] = __floats2half2_rn(a.z, a.w);
    h[2] = __floats2half2_rn(b.x, b.y);
    h[3] = __floats2half2_rn(b.z, b.w);
    ((uint4*)y)[i] = *(uint4*)h;
}

// ---------------------------------------------------------------------------
// fp32 [1024][1024] -> fp16 transposed [1024][1024]
// ---------------------------------------------------------------------------
__global__ __launch_bounds__(1024) void cvt_t(const float* __restrict__ in,
                                              __half* __restrict__ out) {
    __shared__ float t[32][33];
    const int tx = threadIdx.x, ty = threadIdx.y;
    int r = blockIdx.y * 32 + ty;
    int c = blockIdx.x * 32 + tx;
    t[ty][tx] = in[r * EMB + c];
    __syncthreads();
    int ro = blockIdx.x * 32 + ty;
    int co = blockIdx.y * 32 + tx;
    out[ro * EMB + co] = __float2half_rn(t[tx][ty]);
}

// ---------------------------------------------------------------------------
// fp16 transpose: in [SEQ][EMB] per batch  ->  out [EMB][SEQ] per batch
// ---------------------------------------------------------------------------
__global__ __launch_bounds__(1024) void transpose_h(const __half* __restrict__ in,
                                                    __half* __restrict__ out) {
    __shared__ __half t[32][33];
    const size_t zoff = (size_t)blockIdx.z * SEQ * EMB;
    const int tx = threadIdx.x, ty = threadIdx.y;
    int s = blockIdx.y * 32 + ty;
    int e = blockIdx.x * 32 + tx;
    t[ty][tx] = in[zoff + (size_t)s * EMB + e];
    __syncthreads();
    int eo = blockIdx.x * 32 + ty;
    int so = blockIdx.y * 32 + tx;
    out[zoff + (size_t)eo * SEQ + so] = t[tx][ty];
}

// ---------------------------------------------------------------------------
// Small vector precomputes (all fp32 from fp32 inputs)
// ---------------------------------------------------------------------------
// w[e] = sum_a Wk[a][e] * bq[a]
__global__ __launch_bounds__(256) void gemv_w(const float* __restrict__ Wk,
                                              const float* __restrict__ bq,
                                              float* __restrict__ w) {
    int e = blockIdx.x * 256 + threadIdx.x;
    float s = 0.f;
#pragma unroll 8
    for (int a = 0; a < EMB; a++) s += Wk[(size_t)a * EMB + e] * bq[a];
    w[e] = s;
}

// b2[o] = bo[o] + sum_a Wo[o][a] * bv[a]     (warp per o)
__global__ __launch_bounds__(256) void gemv_b2(const float* __restrict__ Wo,
                                               const float* __restrict__ bv,
                                               const float* __restrict__ bo,
                                               float* __restrict__ b2) {
    int o = blockIdx.x * 8 + threadIdx.y;
    int lane = threadIdx.x;
    const float* p = Wo + (size_t)o * EMB;
    float s = 0.f;
    for (int a = lane; a < EMB; a += 32) s += p[a] * bv[a];
#pragma unroll
    for (int off = 16; off; off >>= 1) s += __shfl_xor_sync(0xFFFFFFFFu, s, off);
    if (lane == 0) b2[o] = s + bo[o];
}

// c[row] = (1/32) * sum_e U[row][e] * w[e]   (warp per row, U = fp32 source)
__global__ __launch_bounds__(256) void gemv_c(const float* __restrict__ U,
                                              const float* __restrict__ w,
                                              float* __restrict__ c) {
    size_t row = (size_t)blockIdx.x * 8 + threadIdx.y;
    int lane = threadIdx.x;
    const float* p = U + row * EMB;
    float s = 0.f;
    for (int e = lane; e < EMB; e += 32) s += p[e] * w[e];
#pragma unroll
    for (int off = 16; off; off >>= 1) s += __shfl_xor_sync(0xFFFFFFFFu, s, off);
    if (lane == 0) c[row] = s * (1.f / 32.f);
}

// ---------------------------------------------------------------------------
// HMMA GEMM:  C[m,n] = scale * sum_k A[m,k] * B[n,k]  (+ bias[n], per-z bias stride)
//   A: fp16, row-major [M][K] (ldA)     B: fp16, row-major [N][K] (ldB)
//   EPI==0: fp32 out      EPI==1: fp16 out     (batched by z)
// CTA tile 128x128, BK=64, 8 warps (2x4 grid of 64x32 warp tiles),
// cp.async double-buffered smem (dynamic), ldmatrix, m16n8k16 HMMA.
// Round-6 known-good mainloop; 2 CTAs/SM co-tenancy is load-bearing.
// ---------------------------------------------------------------------------
constexpr int RS = 72;                         // smem row stride (64 + 8 pad)
constexpr int TILE  = 128 * RS * 2;            // 18432 B per tile
constexpr int STAGE = 2 * TILE;                // A + B per stage
constexpr int GEMM_SMEM = 2 * STAGE;           // 73728 B

template <int EPI>
__global__ void __launch_bounds__(256, 2) mma_gemm(
    const __half* __restrict__ A, const __half* __restrict__ B,
    const float* __restrict__ bias, float scale,
    float* __restrict__ Cf, __half* __restrict__ Ch,
    int K, int ldA, int ldB, int ldC,
    size_t strA, size_t strB, size_t strC, size_t strBias)
{
    extern __shared__ __align__(16) char smem[];

    const int tid  = threadIdx.x;
    const int lane = tid & 31;
    const int wid  = tid >> 5;
    const int wm   = (wid >> 2) * 64;      // warp m offset in tile
    const int wn   = (wid & 3) * 32;       // warp n offset in tile
    const int bm   = blockIdx.y * 128;
    const int bn   = blockIdx.x * 128;
    const int bz   = blockIdx.z;

    A += (size_t)bz * strA;
    B += (size_t)bz * strB;
    if (bias) bias += (size_t)bz * strBias;

    const uint32_t sbase = smem_u32(smem);
    const uint32_t sA[2] = { sbase,         sbase + STAGE };
    const uint32_t sB[2] = { sbase + TILE,  sbase + STAGE + TILE };

    // copy one 128x64 fp16 tile (16KB data) : 4 cp.async per thread
    auto load_tile = [&](uint32_t sdst, const __half* src, int ld, int rowBase, int k0) {
#pragma unroll
        for (int i = 0; i < 4; i++) {
            int c  = tid + i * 256;        // 0..1023
            int r  = c >> 3;               // 0..127
            int kc = (c & 7) * 8;          // 0..56
            cp16(sdst + (uint32_t)(r * RS + kc) * 2,
                 src + (size_t)(rowBase + r) * ld + k0 + kc);
        }
    };

    float acc[4][4][4];
#pragma unroll
    for (int i = 0; i < 4; i++)
#pragma unroll
        for (int j = 0; j < 4; j++)
#pragma unroll
            for (int q = 0; q < 4; q++) acc[i][j][q] = 0.f;

    const int nk = K >> 6;

    // prefetch chunk 0
    load_tile(sA[0], A, ldA, bm, 0);
    load_tile(sB[0], B, ldB, bn, 0);
    asm volatile("cp.async.commit_group;");

    for (int c = 0; c < nk; c++) {
        const int buf = c & 1;
        asm volatile("cp.async.wait_group 0;");
        __syncthreads();

        if (c + 1 < nk) {
            const int k0 = (c + 1) << 6;
            load_tile(sA[buf ^ 1], A, ldA, bm, k0);
            load_tile(sB[buf ^ 1], B, ldB, bn, k0);
            asm volatile("cp.async.commit_group;");
        }

        // compute on buf: four k16 steps
#pragma unroll
        for (int ks = 0; ks < 64; ks += 16) {
            uint32_t a[4][4];
#pragma unroll
            for (int i = 0; i < 4; i++) {
                uint32_t addr = sA[buf] +
                    (uint32_t)((wm + i * 16 + (lane & 15)) * RS + ks + ((lane >> 4) << 3)) * 2;
                ldsm4(addr, a[i][0], a[i][1], a[i][2], a[i][3]);
            }
            uint32_t b[4][2];
#pragma unroll
            for (int jj = 0; jj < 2; jj++) {
                int row = wn + jj * 16 + (lane & 7) + ((lane >> 4) << 3);
                int col = ks + (((lane >> 3) & 1) << 3);
                uint32_t addr = sB[buf] + (uint32_t)(row * RS + col) * 2;
                uint32_t r0, r1, r2, r3;
                ldsm4(addr, r0, r1, r2, r3);
                b[2 * jj][0] = r0; b[2 * jj][1] = r1;
                b[2 * jj + 1][0] = r2; b[2 * jj + 1][1] = r3;
            }
#pragma unroll
            for (int i = 0; i < 4; i++)
#pragma unroll
                for (int j = 0; j < 4; j++) {
                    asm volatile(
                        "mma.sync.aligned.m16n8k16.row.col.f32.f16.f16.f32 "
                        "{%0,%1,%2,%3},{%4,%5,%6,%7},{%8,%9},{%0,%1,%2,%3};"
                        : "+f"(acc[i][j][0]), "+f"(acc[i][j][1]),
                          "+f"(acc[i][j][2]), "+f"(acc[i][j][3])
                        : "r"(a[i][0]), "r"(a[i][1]), "r"(a[i][2]), "r"(a[i][3]),
                          "r"(b[j][0]), "r"(b[j][1]));
                }
        }
        __syncthreads();
    }

    // Epilogue
#pragma unroll
    for (int i = 0; i < 4; i++) {
        const int r0 = bm + wm + i * 16 + (lane >> 2);
#pragma unroll
        for (int j = 0; j < 4; j++) {
            const int c0 = bn + wn + j * 8 + 2 * (lane & 3);
            float bia0 = bias ? bias[c0]     : 0.f;
            float bia1 = bias ? bias[c0 + 1] : 0.f;
            float v0 = acc[i][j][0] * scale + bia0;
            float v1 = acc[i][j][1] * scale + bia1;
            float v2 = acc[i][j][2] * scale + bia0;
            float v3 = acc[i][j][3] * scale + bia1;
            const size_t base0 = (size_t)bz * strC + (size_t)r0 * ldC + c0;
            const size_t base1 = base0 + (size_t)8 * ldC;
            if (EPI == 0) {
                *(float2*)(Cf + base0) = make_float2(v0, v1);
                *(float2*)(Cf + base1) = make_float2(v2, v3);
            } else {
                *(__half2*)(Ch + base0) = __floats2half2_rn(v0, v1);
                *(__half2*)(Ch + base1) = __floats2half2_rn(v2, v3);
            }
        }
    }
}

// ---------------------------------------------------------------------------
// Row softmax over length-2048 fp16 rows -> fp16 probabilities
// ---------------------------------------------------------------------------
__global__ __launch_bounds__(256) void softmax_rows(const __half* __restrict__ S,
                                                    __half* __restrict__ P)
{
    const size_t row = blockIdx.x;
    const int tid = threadIdx.x;

    uint4 raw = ((const uint4*)(S + row * (size_t)SEQ))[tid];
    const __half2* hp = (const __half2*)&raw;
    float v[8];
#pragma unroll
    for (int g = 0; g < 4; g++) {
        float2 f = __half22float2(hp[g]);
        v[2 * g] = f.x; v[2 * g + 1] = f.y;
    }

    float m = v[0];
#pragma unroll
    for (int i = 1; i < 8; i++) m = fmaxf(m, v[i]);
#pragma unroll
    for (int o = 16; o > 0; o >>= 1) m = fmaxf(m, __shfl_xor_sync(0xFFFFFFFFu, m, o));
    __shared__ float red[8];
    if ((tid & 31) == 0) red[tid >> 5] = m;
    __syncthreads();
    m = red[0];
#pragma unroll
    for (int w = 1; w < 8; w++) m = fmaxf(m, red[w]);
    __syncthreads();

    float s = 0.f;
#pragma unroll
    for (int i = 0; i < 8; i++) { v[i] = __expf(v[i] - m); s += v[i]; }
#pragma unroll
    for (int o = 16; o > 0; o >>= 1) s += __shfl_xor_sync(0xFFFFFFFFu, s, o);
    if ((tid & 31) == 0) red[tid >> 5] = s;
    __syncthreads();
    s = 0.f;
#pragma unroll
    for (int w = 0; w < 8; w++) s += red[w];
    const float inv = 1.f / s;

    __half2 h[4];
#pragma unroll
    for (int g = 0; g < 4; g++)
        h[g] = __floats2half2_rn(v[2 * g] * inv, v[2 * g + 1] * inv);
    ((uint4*)(P + row * (size_t)SEQ))[tid] = *(uint4*)h;
}

// ---------------------------------------------------------------------------
// Launcher
// ---------------------------------------------------------------------------
extern "C" void kernel_launch(void* const* d_in, const int* in_sizes, int n_in,
                              void* d_out, int out_size)
{
    const float* target = (const float*)d_in[0];
    const float* source = (const float*)d_in[1];
    const float* Wq = (const float*)d_in[2];
    const float* bq = (const float*)d_in[3];
    const float* Wk = (const float*)d_in[4];
    const float* bk = (const float*)d_in[5];
    const float* Wv = (const float*)d_in[6];
    const float* bv = (const float*)d_in[7];
    const float* Wo = (const float*)d_in[8];
    const float* bo = (const float*)d_in[9];
    float* out = (float*)d_out;
    (void)bk;   // cancels in softmax (constant per row)

    __half *pT, *pU, *pW, *pG, *pH, *pQ2, *pV2, *pVt, *pP, *pS;
    float *pc, *pw, *pb2;
    cudaGetSymbolAddress((void**)&pT,  g_T16);
    cudaGetSymbolAddress((void**)&pU,  g_U16);
    cudaGetSymbolAddress((void**)&pW,  g_W16);
    cudaGetSymbolAddress((void**)&pG,  g_G);
    cudaGetSymbolAddress((void**)&pH,  g_H);
    cudaGetSymbolAddress((void**)&pQ2, g_Q2);
    cudaGetSymbolAddress((void**)&pV2, g_V2);
    cudaGetSymbolAddress((void**)&pVt, g_Vt);
    cudaGetSymbolAddress((void**)&pP,  g_P16);
    cudaGetSymbolAddress((void**)&pS,  g_S16);
    cudaGetSymbolAddress((void**)&pc,  g_c);
    cudaGetSymbolAddress((void**)&pw,  g_w);
    cudaGetSymbolAddress((void**)&pb2, g_b2);

    cudaFuncSetAttribute(mma_gemm<0>, cudaFuncAttributeMaxDynamicSharedMemorySize, GEMM_SMEM);
    cudaFuncSetAttribute(mma_gemm<1>, cudaFuncAttributeMaxDynamicSharedMemorySize, GEMM_SMEM);

    const size_t WS = (size_t)EMB * EMB;
    const dim3 blk(256);

    // ---- conversions: T, U, Wo plain; Wq/Wk/Wv transposed
    {
        size_t n8 = MT * EMB / 8;             // 2M
        cvt_h<<<(unsigned)((n8 + 255) / 256), blk>>>(target, pT, n8);
        cvt_h<<<(unsigned)((n8 + 255) / 256), blk>>>(source, pU, n8);
        size_t w8 = WS / 8;                   // 128K
        cvt_h<<<(unsigned)((w8 + 255) / 256), blk>>>(Wo, pW + 3 * WS, w8);
        cvt_t<<<dim3(32, 32), dim3(32, 32)>>>(Wq, pW + 0 * WS);
        cvt_t<<<dim3(32, 32), dim3(32, 32)>>>(Wk, pW + 1 * WS);
        cvt_t<<<dim3(32, 32), dim3(32, 32)>>>(Wv, pW + 2 * WS);
    }

    // ---- vector precomputes
    gemv_w <<<EMB / 256, blk>>>(Wk, bq, pw);
    gemv_c <<<(unsigned)(MT / 8), dim3(32, 8)>>>(source, pw, pc);
    gemv_b2<<<EMB / 8, dim3(32, 8)>>>(Wo, bv, bo, pb2);

    // ---- folded weights: G'[e][d] = sum_a WkT[e,a] WqT[d,a];  H[o][e] = sum_a Wo[o,a] WvT[e,a]
    mma_gemm<1><<<dim3(8, 8), blk, GEMM_SMEM>>>(pW + 1 * WS, pW + 0 * WS, nullptr, 1.f,
        nullptr, pG, EMB, EMB, EMB, EMB, 0, 0, 0, 0);
    mma_gemm<1><<<dim3(8, 8), blk, GEMM_SMEM>>>(pW + 3 * WS, pW + 2 * WS, nullptr, 1.f,
        nullptr, pH, EMB, EMB, EMB, EMB, 0, 0, 0, 0);

    const dim3 gProj(EMB / 128, (unsigned)(MT / 128), 1);   // 8 x 128

    // ---- Q2 = T * G   (C[t,e] = sum_d T[t,d] G'[e,d])
    mma_gemm<1><<<gProj, blk, GEMM_SMEM>>>(pT, pG, nullptr, 1.f, nullptr, pQ2,
                                           EMB, EMB, EMB, EMB, 0, 0, 0, 0);
    // ---- V2 = U * H^T (C[s,o] = sum_e U[s,e] H[o,e])
    mma_gemm<1><<<gProj, blk, GEMM_SMEM>>>(pU, pH, nullptr, 1.f, nullptr, pV2,
                                           EMB, EMB, EMB, EMB, 0, 0, 0, 0);

    // ---- transpose V2: [b][s][o] -> [b][o][s]
    transpose_h<<<dim3(EMB / 32, SEQ / 32, BATCH), dim3(32, 32)>>>(pV2, pVt);

    // ---- scores: S[b][t][s] = Q2[b]_t . U[b]_s / 32 + c[b][s]   -> fp16
    mma_gemm<1><<<dim3(SEQ / 128, SEQ / 128, BATCH), blk, GEMM_SMEM>>>(
        pQ2, pU, pc, 1.f / 32.f, nullptr, pS,
        EMB, EMB, EMB, SEQ,
        (size_t)SEQ * EMB, (size_t)SEQ * EMB, (size_t)SEQ * SEQ, (size_t)SEQ);

    // ---- softmax -> fp16 P
    softmax_rows<<<BATCH * SEQ, blk>>>(pS, pP);

    // ---- out[b][t][o] = sum_s P[b][t][s] Vt[b][o][s] + b2[o]   -> fp32
    mma_gemm<0><<<dim3(EMB / 128, SEQ / 128, BATCH), blk, GEMM_SMEM>>>(
        pP, pVt, pb2, 1.f, out, nullptr,
        SEQ, SEQ, SEQ, EMB,
        (size_t)SEQ * SEQ, (size_t)SEQ * EMB, (size_t)SEQ * EMB, 0);
}